// round 10
// baseline (speedup 1.0000x reference)
#include <cuda_runtime.h>

// QLSTM collapsed analytically:
//   quantum_gate(comb, p)[:, k] = prod_{j<=k} cos(p_j) * cos(comb_j)
// Only k < H=4 used; comb[0:4] = x  => gates depend only on x_t.
// Per (b,k): c = f*c + i*g ; h = o*tanh(c); gate args in [-1,1], |c| <= 1.26.
//
// Mapping: block = 512 thr = 16 warps = 8 batch els x full T.
//   warp = one 8-step t-segment; lane = (chunk 0..3)*8 + bsub(0..7); CHUNK=2.
//   8 bsub lanes at one t = one 128B line -> 4 L1 wavefronts per LDG/STG
//   (vs 16 in previous layouts).
// Pass 1: load x once, cache f, i*g, o; chunk affine aggregates.
// Warp scan (2 rounds) over 4 chunks; 16 segments linked via smem affine fold.
// Pass 2: pure-register recurrence + streaming stores. No reloads.

#define T_STEPS 128
#define BATCH   4096
#define CHUNK   2
#define FULLMASK 0xffffffffu

// sigmoid(2u), |u|<=0.5 : 0.5 + u*q(u^2); tanh Taylor deg-9 halved, err ~2e-6
__device__ __forceinline__ float sig_poly(float u) {
    float w = u * u;
    float q = fmaf(w, fmaf(w, fmaf(w, fmaf(w, 0.010934744f,
                                              -0.026984127f),
                                       0.066666667f),
                               -0.166666667f),
                       0.5f);
    return fmaf(u, q, 0.5f);
}
// tanh Pade(5,4); err ~4e-8 at |z|<=1, ~5e-7 at |z|<=1.3
__device__ __forceinline__ float tanh_p54(float z) {
    float w = z * z;
    float n = z * fmaf(w, fmaf(w, 1.0f, 105.0f), 945.0f);
    float d =     fmaf(w, fmaf(w, 15.0f, 420.0f), 945.0f);
    return __fdividef(n, d);
}

__global__ void __launch_bounds__(512, 2) qlstm_kernel(
    const float* __restrict__ inp,   // [T, B, 4]
    const float* __restrict__ prm_f, // [8]
    const float* __restrict__ prm_i,
    const float* __restrict__ prm_g,
    const float* __restrict__ prm_o,
    float* __restrict__ out)         // [T*B*4 + B*4 + B*4]
{
    const int seg   = threadIdx.x >> 5;      // t-segment 0..15 (8 steps each)
    const int lane  = threadIdx.x & 31;
    const int bsub  = lane & 7;               // batch offset within block
    const int chunk = (lane >> 3);            // 0..3 (2 steps each)
    const int b     = blockIdx.x * 8 + bsub;
    const int t0    = seg * 8 + chunk * CHUNK;

    // per-segment total affine maps, per (seg, bsub): float4 over k
    __shared__ float4 sF[16][8];
    __shared__ float4 sC[16][8];

    // per-k parameter prefix products (uniform)
    float AFh[4], AIh[4], AG[4], AOh[4];
    {
        float pf_ = 1.0f, pi_ = 1.0f, pg_ = 1.0f, po_ = 1.0f;
#pragma unroll
        for (int j = 0; j < 4; ++j) {
            pf_ *= __cosf(prm_f[j]);
            pi_ *= __cosf(prm_i[j]);
            pg_ *= __cosf(prm_g[j]);
            po_ *= __cosf(prm_o[j]);
            AFh[j] = 0.5f * pf_;   // sigmoid poly takes arg/2
            AIh[j] = 0.5f * pi_;
            AG[j]  = pg_;
            AOh[j] = 0.5f * po_;
        }
    }

    const float4* __restrict__ xin = (const float4*)inp;

    // ---- pass 1: load once, cache gates, accumulate chunk affine map ----
    float Fc[CHUNK][4], Gc[CHUNK][4], Oc[CHUNK][4];
    float cl0 = 0.f, cl1 = 0.f, cl2 = 0.f, cl3 = 0.f;
    float pf0 = 1.f, pf1 = 1.f, pf2 = 1.f, pf3 = 1.f;

#pragma unroll
    for (int it = 0; it < CHUNK; ++it) {
        float4 x = xin[(t0 + it) * BATCH + b];
        float P0 = __cosf(x.x);
        float P1 = P0 * __cosf(x.y);
        float P2 = P1 * __cosf(x.z);
        float P3 = P2 * __cosf(x.w);

        float f, i, g, ig;
        f = sig_poly(AFh[0] * P0); i = sig_poly(AIh[0] * P0); g = tanh_p54(AG[0] * P0);
        ig = i * g; Fc[it][0] = f; Gc[it][0] = ig; Oc[it][0] = sig_poly(AOh[0] * P0);
        cl0 = fmaf(f, cl0, ig); pf0 *= f;

        f = sig_poly(AFh[1] * P1); i = sig_poly(AIh[1] * P1); g = tanh_p54(AG[1] * P1);
        ig = i * g; Fc[it][1] = f; Gc[it][1] = ig; Oc[it][1] = sig_poly(AOh[1] * P1);
        cl1 = fmaf(f, cl1, ig); pf1 *= f;

        f = sig_poly(AFh[2] * P2); i = sig_poly(AIh[2] * P2); g = tanh_p54(AG[2] * P2);
        ig = i * g; Fc[it][2] = f; Gc[it][2] = ig; Oc[it][2] = sig_poly(AOh[2] * P2);
        cl2 = fmaf(f, cl2, ig); pf2 *= f;

        f = sig_poly(AFh[3] * P3); i = sig_poly(AIh[3] * P3); g = tanh_p54(AG[3] * P3);
        ig = i * g; Fc[it][3] = f; Gc[it][3] = ig; Oc[it][3] = sig_poly(AOh[3] * P3);
        cl3 = fmaf(f, cl3, ig); pf3 *= f;
    }

    // ---- warp scan over 4 chunks (lanes stride 8, same bsub) ----
    float F0 = pf0, C0 = cl0, F1 = pf1, C1 = cl1;
    float F2 = pf2, C2 = cl2, F3 = pf3, C3 = cl3;
    {
        float Fo0 = __shfl_up_sync(FULLMASK, F0, 8), Co0 = __shfl_up_sync(FULLMASK, C0, 8);
        float Fo1 = __shfl_up_sync(FULLMASK, F1, 8), Co1 = __shfl_up_sync(FULLMASK, C1, 8);
        float Fo2 = __shfl_up_sync(FULLMASK, F2, 8), Co2 = __shfl_up_sync(FULLMASK, C2, 8);
        float Fo3 = __shfl_up_sync(FULLMASK, F3, 8), Co3 = __shfl_up_sync(FULLMASK, C3, 8);
        if (chunk >= 1) {
            C0 = fmaf(F0, Co0, C0); F0 *= Fo0;
            C1 = fmaf(F1, Co1, C1); F1 *= Fo1;
            C2 = fmaf(F2, Co2, C2); F2 *= Fo2;
            C3 = fmaf(F3, Co3, C3); F3 *= Fo3;
        }
        Fo0 = __shfl_up_sync(FULLMASK, F0, 16); Co0 = __shfl_up_sync(FULLMASK, C0, 16);
        Fo1 = __shfl_up_sync(FULLMASK, F1, 16); Co1 = __shfl_up_sync(FULLMASK, C1, 16);
        Fo2 = __shfl_up_sync(FULLMASK, F2, 16); Co2 = __shfl_up_sync(FULLMASK, C2, 16);
        Fo3 = __shfl_up_sync(FULLMASK, F3, 16); Co3 = __shfl_up_sync(FULLMASK, C3, 16);
        if (chunk >= 2) {
            C0 = fmaf(F0, Co0, C0); F0 *= Fo0;
            C1 = fmaf(F1, Co1, C1); F1 *= Fo1;
            C2 = fmaf(F2, Co2, C2); F2 *= Fo2;
            C3 = fmaf(F3, Co3, C3); F3 *= Fo3;
        }
    }

    // publish this segment's total affine map (chunk 3 = inclusive total)
    if (chunk == 3) {
        sF[seg][bsub] = make_float4(F0, F1, F2, F3);
        sC[seg][bsub] = make_float4(C0, C1, C2, C3);
    }

    // exclusive prefix within this segment
    float Fe0 = __shfl_up_sync(FULLMASK, F0, 8), Ce0 = __shfl_up_sync(FULLMASK, C0, 8);
    float Fe1 = __shfl_up_sync(FULLMASK, F1, 8), Ce1 = __shfl_up_sync(FULLMASK, C1, 8);
    float Fe2 = __shfl_up_sync(FULLMASK, F2, 8), Ce2 = __shfl_up_sync(FULLMASK, C2, 8);
    float Fe3 = __shfl_up_sync(FULLMASK, F3, 8), Ce3 = __shfl_up_sync(FULLMASK, C3, 8);
    if (chunk == 0) {
        Fe0 = 1.f; Ce0 = 0.f; Fe1 = 1.f; Ce1 = 0.f;
        Fe2 = 1.f; Ce2 = 0.f; Fe3 = 1.f; Ce3 = 0.f;
    }

    __syncthreads();

    // fold preceding segments' maps (ascending): c = C_q + F_q * c
    float ch0 = 0.f, ch1 = 0.f, ch2 = 0.f, ch3 = 0.f;
#pragma unroll
    for (int q = 0; q < 15; ++q) {
        if (seg > q) {               // uniform per warp -> real branch
            float4 Fq = sF[q][bsub];
            float4 Cq = sC[q][bsub];
            ch0 = fmaf(Fq.x, ch0, Cq.x);
            ch1 = fmaf(Fq.y, ch1, Cq.y);
            ch2 = fmaf(Fq.z, ch2, Cq.z);
            ch3 = fmaf(Fq.w, ch3, Cq.w);
        }
    }

    float c0 = fmaf(Fe0, ch0, Ce0);
    float c1 = fmaf(Fe1, ch1, Ce1);
    float c2 = fmaf(Fe2, ch2, Ce2);
    float c3 = fmaf(Fe3, ch3, Ce3);

    // ---- pass 2: pure-register recurrence, emit h ----
    float4* __restrict__ out4 = (float4*)out;
    float h0 = 0.f, h1 = 0.f, h2 = 0.f, h3 = 0.f;

#pragma unroll
    for (int it = 0; it < CHUNK; ++it) {
        c0 = fmaf(Fc[it][0], c0, Gc[it][0]);
        c1 = fmaf(Fc[it][1], c1, Gc[it][1]);
        c2 = fmaf(Fc[it][2], c2, Gc[it][2]);
        c3 = fmaf(Fc[it][3], c3, Gc[it][3]);

        h0 = Oc[it][0] * tanh_p54(c0);   // |c| <= 1.26 -> p54 err ~5e-7
        h1 = Oc[it][1] * tanh_p54(c1);
        h2 = Oc[it][2] * tanh_p54(c2);
        h3 = Oc[it][3] * tanh_p54(c3);

        __stcs(&out4[(t0 + it) * BATCH + b], make_float4(h0, h1, h2, h3));
    }

    // final state: seg 15, chunk 3, it = CHUNK-1 (t = 127)
    if (seg == 15 && chunk == 3) {
        out4[T_STEPS * BATCH + b]         = make_float4(h0, h1, h2, h3); // hx
        out4[T_STEPS * BATCH + BATCH + b] = make_float4(c0, c1, c2, c3); // cx
    }
}

extern "C" void kernel_launch(void* const* d_in, const int* in_sizes, int n_in,
                              void* d_out, int out_size) {
    (void)in_sizes; (void)n_in; (void)out_size;
    const float* inp   = (const float*)d_in[0];
    const float* prm_f = (const float*)d_in[1];
    const float* prm_i = (const float*)d_in[2];
    const float* prm_g = (const float*)d_in[3];
    const float* prm_o = (const float*)d_in[4];
    float* out = (float*)d_out;

    // 512 blocks x 512 threads: block = 8 batch els x full T (16 segments)
    qlstm_kernel<<<512, 512>>>(inp, prm_f, prm_i, prm_g, prm_o, out);
}